// round 9
// baseline (speedup 1.0000x reference)
#include <cuda_runtime.h>
#include <cstdint>

#define BS 4096
#define D  100
#define H  16
#define P  2

#define BPB 8
#define TSPLIT 4
#define TRANGE (D / TSPLIT)        // 25
#define THREADS 224                // 7 warps; 200 active units + 24 helpers
#define UNITS (TRANGE * BPB)       // 200
#define GRID ((BS / BPB) * TSPLIT) // 2048

// ---- device scratch (allocation-free rule) ----
// W0C[(g*100+t)*16 + i] = float4{ W0[t,i,4g..4g+3] }
__device__ float4 g_W0C[25 * D * H];   // 640 KB
// W1C[(ci*100+t)*16 + i2] = float4{ W1[t,i2,4ci..4ci+3] }
__device__ float4 g_W1C[4 * D * H];    // 102.4 KB

__device__ __forceinline__ float leaky1(float v) { return fmaxf(v, 0.01f * v); }

// ---------------- prep: weight relayout ----------------
__global__ void prep_kernel(const float* __restrict__ W0,
                            const float* __restrict__ W1)
{
    int n = blockIdx.x * blockDim.x + threadIdx.x;
    if (n < 25 * D * H) {                       // 40000: W0 -> g-major float4
        int g = n / (D * H);
        int r = n - g * (D * H);
        int t = r >> 4;
        int i = r & 15;
        g_W0C[n] = *(const float4*)(W0 + (size_t)(t * H + i) * D + 4 * g);
    } else if (n < 25 * D * H + 4 * D * H) {    // 6400: W1 -> chunk-major float4
        int k  = n - 25 * D * H;
        int ci = k / (D * H);
        int r  = k - ci * (D * H);
        int t  = r >> 4;
        int i2 = r & 15;
        g_W1C[k] = *(const float4*)(W1 + (size_t)(t * H + i2) * H + 4 * ci);
    }
}

// ---------------- main: thread = (t, c); weights staged via SMEM ----------------
__global__ __launch_bounds__(THREADS, 5)
void basemodel_kernel(const float* __restrict__ x,
                      const float* __restrict__ log_alpha,
                      const float* __restrict__ noise,
                      const float* __restrict__ b0,
                      const float* __restrict__ b1,
                      const float* __restrict__ W2,
                      const float* __restrict__ b2,
                      float* __restrict__ out)
{
    __shared__ float4 s_wbuf[TRANGE * 17];              // 425 f4, 6.8 KB (padded rows)
    __shared__ __align__(16) float s_x[BPB][108];       // 3.5 KB (pad 108 -> bank-clean)
    __shared__ unsigned char s_mask[TRANGE * 104];      // 2.6 KB (pad 104 -> u32-aligned)

    const int tid = threadIdx.x;
    const int bx  = blockIdx.x;
    const int b0i = (bx >> 2) * BPB;                    // batch group
    const int t0  = (bx & 3) * TRANGE;                  // t slice

    // ---- stage x for 8 batches ----
    for (int m = tid; m < BPB * D; m += THREADS) {
        int c = m / D, j = m - c * D;
        s_x[c][j] = x[(size_t)(b0i + c) * D + j];
    }
    // ---- Phase A: Gumbel-hard mask bytes (8 c-bits per (t,j)) ----
    {
        const float* nz = noise + (size_t)b0i * D * D;
        for (int m = tid; m < D * TRANGE; m += THREADS) {
            int j  = m / TRANGE;
            int tl = m - j * TRANGE;
            int gi = j * D + t0 + tl;                   // coalesced runs of 25
            float la = log_alpha[gi];
            unsigned bits = 0;
            #pragma unroll
            for (int c = 0; c < 8; ++c)
                bits |= ((la + nz[(size_t)c * D * D + gi]) > 0.0f) ? (1u << c) : 0u;
            if (j == t0 + tl) bits = 0;                 // no-self-loop
            s_mask[tl * 104 + j] = (unsigned char)bits;
        }
    }

    const bool active = (tid < UNITS);
    const int tl = tid >> 3;                            // local t (0..24)
    const int c  = tid & 7;                             // batch lane (0..7)

    // ---- Phase B: layer0, W0 staged per g (double-synced, reg-prefetched) ----
    float h1[16];
    #pragma unroll
    for (int i = 0; i < 16; ++i) h1[i] = 0.0f;

    // prefetch g=0 stage data (400 float4, contiguous, coalesced)
    float4 r0 = g_W0C[(size_t)(0 * D + t0) * 16 + tid];
    float4 r1;
    if (tid < 400 - THREADS) r1 = g_W0C[(size_t)(0 * D + t0) * 16 + tid + THREADS];

    for (int g = 0; g < 25; ++g) {
        __syncthreads();                                // buffer free (prev compute done)
        {
            int s = tid;
            s_wbuf[(s >> 4) * 17 + (s & 15)] = r0;
            if (tid < 400 - THREADS) {
                int s2 = tid + THREADS;
                s_wbuf[(s2 >> 4) * 17 + (s2 & 15)] = r1;
            }
        }
        if (g < 24) {
            const float4* src = g_W0C + (size_t)((g + 1) * D + t0) * 16;
            r0 = src[tid];
            if (tid < 400 - THREADS) r1 = src[tid + THREADS];
        }
        __syncthreads();                                // buffer ready
        if (active) {
            unsigned mw = *(const unsigned*)(s_mask + tl * 104 + 4 * g);
            float4 xv  = *(const float4*)(s_x[c] + 4 * g);
            unsigned mc = mw >> c;                      // bit 8*jj = mask for jj
            float xm0 = (mc & 0x1u)        ? xv.x : 0.0f;
            float xm1 = (mc & 0x100u)      ? xv.y : 0.0f;
            float xm2 = (mc & 0x10000u)    ? xv.z : 0.0f;
            float xm3 = (mc & 0x1000000u)  ? xv.w : 0.0f;
            #pragma unroll
            for (int i = 0; i < 16; ++i) {
                float4 w = s_wbuf[tl * 17 + i];         // broadcast, conflict-free
                h1[i] = fmaf(w.x, xm0, h1[i]);
                h1[i] = fmaf(w.y, xm1, h1[i]);
                h1[i] = fmaf(w.z, xm2, h1[i]);
                h1[i] = fmaf(w.w, xm3, h1[i]);
            }
        }
    }
    if (active) {
        const float4* bp = (const float4*)(b0 + (size_t)(t0 + tl) * 16);
        #pragma unroll
        for (int q = 0; q < 4; ++q) {
            float4 bv = bp[q];
            h1[4 * q + 0] = leaky1(h1[4 * q + 0] + bv.x);
            h1[4 * q + 1] = leaky1(h1[4 * q + 1] + bv.y);
            h1[4 * q + 2] = leaky1(h1[4 * q + 2] + bv.z);
            h1[4 * q + 3] = leaky1(h1[4 * q + 3] + bv.w);
        }
    }

    // ---- Phase C: layer1, W1 staged in 4 chunks; thread-local (no shuffles) ----
    float h2[16];
    #pragma unroll
    for (int i = 0; i < 16; ++i) h2[i] = 0.0f;

    r0 = g_W1C[(size_t)(0 * D + t0) * 16 + tid];
    if (tid < 400 - THREADS) r1 = g_W1C[(size_t)(0 * D + t0) * 16 + tid + THREADS];

    for (int ci = 0; ci < 4; ++ci) {
        __syncthreads();
        {
            int s = tid;
            s_wbuf[(s >> 4) * 17 + (s & 15)] = r0;
            if (tid < 400 - THREADS) {
                int s2 = tid + THREADS;
                s_wbuf[(s2 >> 4) * 17 + (s2 & 15)] = r1;
            }
        }
        if (ci < 3) {
            const float4* src = g_W1C + (size_t)((ci + 1) * D + t0) * 16;
            r0 = src[tid];
            if (tid < 400 - THREADS) r1 = src[tid + THREADS];
        }
        __syncthreads();
        if (active) {
            float ha = h1[4 * ci + 0];
            float hb = h1[4 * ci + 1];
            float hc = h1[4 * ci + 2];
            float hd = h1[4 * ci + 3];
            #pragma unroll
            for (int i2 = 0; i2 < 16; ++i2) {
                float4 w = s_wbuf[tl * 17 + i2];
                h2[i2] = fmaf(w.x, ha, h2[i2]);
                h2[i2] = fmaf(w.y, hb, h2[i2]);
                h2[i2] = fmaf(w.z, hc, h2[i2]);
                h2[i2] = fmaf(w.w, hd, h2[i2]);
            }
        }
    }

    if (!active) return;

    {
        const float4* bp = (const float4*)(b1 + (size_t)(t0 + tl) * 16);
        #pragma unroll
        for (int q = 0; q < 4; ++q) {
            float4 bv = bp[q];
            h2[4 * q + 0] = leaky1(h2[4 * q + 0] + bv.x);
            h2[4 * q + 1] = leaky1(h2[4 * q + 1] + bv.y);
            h2[4 * q + 2] = leaky1(h2[4 * q + 2] + bv.z);
            h2[4 * q + 3] = leaky1(h2[4 * q + 3] + bv.w);
        }
    }

    // ---- Phase D: output layer, thread-local, direct store ----
    const float4* w2p = (const float4*)(W2 + (size_t)(t0 + tl) * P * H);
    float p0 = 0.0f, p1 = 0.0f;
    #pragma unroll
    for (int q = 0; q < 4; ++q) {
        float4 wa = w2p[q];                              // W2[t,0,4q..]
        float4 wb = w2p[4 + q];                          // W2[t,1,4q..]
        p0 = fmaf(wa.x, h2[4 * q + 0], p0); p0 = fmaf(wa.y, h2[4 * q + 1], p0);
        p0 = fmaf(wa.z, h2[4 * q + 2], p0); p0 = fmaf(wa.w, h2[4 * q + 3], p0);
        p1 = fmaf(wb.x, h2[4 * q + 0], p1); p1 = fmaf(wb.y, h2[4 * q + 1], p1);
        p1 = fmaf(wb.z, h2[4 * q + 2], p1); p1 = fmaf(wb.w, h2[4 * q + 3], p1);
    }
    float2 bb = *(const float2*)(b2 + (size_t)(t0 + tl) * P);
    *(float2*)(out + (size_t)(b0i + c) * D * P + (size_t)(t0 + tl) * P) =
        make_float2(p0 + bb.x, p1 + bb.y);
}

extern "C" void kernel_launch(void* const* d_in, const int* in_sizes, int n_in,
                              void* d_out, int out_size)
{
    const float* x         = (const float*)d_in[0];
    const float* log_alpha = (const float*)d_in[1];
    const float* noise     = (const float*)d_in[2];
    const float* W0        = (const float*)d_in[3];
    const float* b0        = (const float*)d_in[4];
    const float* W1        = (const float*)d_in[5];
    const float* b1        = (const float*)d_in[6];
    const float* W2        = (const float*)d_in[7];
    const float* b2        = (const float*)d_in[8];
    float* out             = (float*)d_out;

    const int prep_n = 25 * D * H + 4 * D * H;           // 46400
    prep_kernel<<<(prep_n + 255) / 256, 256>>>(W0, W1);

    basemodel_kernel<<<GRID, THREADS>>>(
        x, log_alpha, noise, b0, b1, W2, b2, out);
}